// round 1
// baseline (speedup 1.0000x reference)
#include <cuda_runtime.h>
#include <math.h>

#define FCOS_INF 1000000000.0f
#define MAXG 64

// Accumulators: [0]=cls_sum, [1]=box_weighted_sum, [2]=w_sum, [3]=center_sum, [4]=num_pos
__device__ double g_acc[5];

__global__ void fcos_zero_kernel() {
    if (threadIdx.x < 5) g_acc[threadIdx.x] = 0.0;
}

__device__ __forceinline__ float log_sigmoid_f(float x) {
    // log(sigmoid(x)) = min(x,0) - log1p(exp(-|x|))
    return fminf(x, 0.0f) - log1pf(expf(-fabsf(x)));
}

__global__ void __launch_bounds__(256)
fcos_main_kernel(const float* __restrict__ loc,
                 const float* __restrict__ cls_pred,
                 const float* __restrict__ box_pred,
                 const float* __restrict__ center_pred,
                 const float* __restrict__ bboxes,
                 const int*   __restrict__ gt_labels,
                 const float* __restrict__ spt,
                 const float* __restrict__ soi,
                 int N, int G, int C) {
    __shared__ float sbb[MAXG * 6];
    __shared__ float sarea[MAXG];
    __shared__ int   slab[MAXG];
    __shared__ float sred[8 * 5];   // up to 8 warps, 5 accumulators

    const int b = blockIdx.y;

    for (int t = threadIdx.x; t < G * 6; t += blockDim.x)
        sbb[t] = bboxes[b * G * 6 + t];
    for (int t = threadIdx.x; t < G; t += blockDim.x)
        slab[t] = gt_labels[b * G + t];
    __syncthreads();
    for (int t = threadIdx.x; t < G; t += blockDim.x) {
        const float* q = sbb + t * 6;
        sarea[t] = (q[3] - q[0]) * (q[4] - q[1]) * (q[5] - q[2]);
    }
    __syncthreads();

    const int i = blockIdx.x * blockDim.x + threadIdx.x;

    float cls_sum = 0.f, box_sum = 0.f, w_sum = 0.f, ctr_sum = 0.f, npos = 0.f;

    if (i < N) {
        const float x = loc[i * 3 + 0];
        const float y = loc[i * 3 + 1];
        const float z = loc[i * 3 + 2];
        const float s  = spt[i];
        const float lo = soi[i * 2 + 0];
        const float hi = soi[i * 2 + 1];

        float best = FCOS_INF;
        int bg = -1;
        float Tl = 1.f, Tt = 1.f, Tf = 1.f, Tr = 1.f, Tb = 1.f, Ta = 1.f;

        for (int g = 0; g < G; ++g) {
            const float b0 = sbb[g * 6 + 0], b1 = sbb[g * 6 + 1], b2 = sbb[g * 6 + 2];
            const float b3 = sbb[g * 6 + 3], b4 = sbb[g * 6 + 4], b5 = sbb[g * 6 + 5];

            const float el = x - b0, et = y - b1, ef = z - b2;
            const float er = b3 - x, eb = b4 - y, ea = b5 - z;

            const float mx = fmaxf(fmaxf(fmaxf(el, et), fmaxf(ef, er)), fmaxf(eb, ea));
            const bool cared = (mx >= lo) && (mx <= hi);

            const float cx = (b0 + b3) * 0.5f, cy = (b1 + b4) * 0.5f, cz = (b2 + b5) * 0.5f;
            const float cminx = fmaxf(cx - s, b0), cmaxx = fminf(cx + s, b3);
            const float cminy = fmaxf(cy - s, b1), cmaxy = fminf(cy + s, b4);
            const float cminz = fmaxf(cz - s, b2), cmaxz = fminf(cz + s, b5);
            const float dmin = fminf(fminf(fminf(x - cminx, cmaxx - x),
                                           fminf(y - cminy, cmaxy - y)),
                                     fminf(z - cminz, cmaxz - z));
            const bool is_in = dmin > 0.0f;

            const float ar = (is_in && cared) ? sarea[g] : FCOS_INF;
            if (ar < best) {   // strict < => first-occurrence argmin, matches jnp.argmin
                best = ar; bg = g;
                Tl = el; Tt = et; Tf = ef; Tr = er; Tb = eb; Ta = ea;
            }
        }

        const int label = (bg >= 0) ? slab[bg] : 0;

        // ---- focal loss over C classes (always) ----
        const float* cp = cls_pred + ((size_t)b * N + i) * C;
        #pragma unroll 8
        for (int c = 0; c < C; ++c) {
            const float xl = cp[c];
            const float p   = 1.0f / (1.0f + expf(-xl));
            const float ls  = log_sigmoid_f(xl);
            const float lns = log_sigmoid_f(-xl);
            const float one_m_p = 1.0f - p;
            const bool posc = (label == c + 1);
            cls_sum += posc ? (-0.25f * one_m_p * one_m_p * ls)
                            : (-0.75f * p * p * lns);
        }

        // ---- box + centerness losses (only when positive) ----
        if (label > 0) {
            const float lrmn = fminf(Tl, Tr), lrmx = fmaxf(Tl, Tr);
            const float tbmn = fminf(Tt, Tb), tbmx = fmaxf(Tt, Tb);
            const float fbmn = fminf(Tf, Ta), fbmx = fmaxf(Tf, Ta);
            float cc = (lrmn / lrmx) * (tbmn / tbmx) * (fbmn / fbmx);
            cc = fminf(fmaxf(cc, 1e-8f), 1.0f);
            const float ctr_t = sqrtf(cc);

            const float* bp = box_pred + ((size_t)b * N + i) * 6;
            const float p0 = bp[0], p1 = bp[1], p2 = bp[2];
            const float p3 = bp[3], p4 = bp[4], p5 = bp[5];

            const float pv = (p0 + p3) * (p1 + p4) * (p2 + p5);
            const float tv = (Tl + Tr) * (Tt + Tb) * (Tf + Ta);
            const float inter = (fminf(p0, Tl) + fminf(p3, Tr)) *
                                (fminf(p1, Tt) + fminf(p4, Tb)) *
                                (fminf(p2, Tf) + fminf(p5, Ta));
            const float uni = pv + tv - inter;
            const float iou = (inter + 1.0f) / (uni + 1.0f);
            const float iou_loss = -logf(fmaxf(iou, 1e-6f));

            box_sum += iou_loss * ctr_t;
            w_sum   += ctr_t;

            const float ct = center_pred[(size_t)b * N + i];
            const float bce = fmaxf(ct, 0.0f) - ct * ctr_t + log1pf(expf(-fabsf(ct)));
            ctr_sum += bce;
            npos += 1.0f;
        }
    }

    // ---- warp reduce ----
    #pragma unroll
    for (int off = 16; off > 0; off >>= 1) {
        cls_sum += __shfl_down_sync(0xffffffffu, cls_sum, off);
        box_sum += __shfl_down_sync(0xffffffffu, box_sum, off);
        w_sum   += __shfl_down_sync(0xffffffffu, w_sum,   off);
        ctr_sum += __shfl_down_sync(0xffffffffu, ctr_sum, off);
        npos    += __shfl_down_sync(0xffffffffu, npos,    off);
    }
    const int lane = threadIdx.x & 31;
    const int wid  = threadIdx.x >> 5;
    if (lane == 0) {
        sred[wid * 5 + 0] = cls_sum;
        sred[wid * 5 + 1] = box_sum;
        sred[wid * 5 + 2] = w_sum;
        sred[wid * 5 + 3] = ctr_sum;
        sred[wid * 5 + 4] = npos;
    }
    __syncthreads();
    if (threadIdx.x == 0) {
        double a0 = 0, a1 = 0, a2 = 0, a3 = 0, a4 = 0;
        const int nw = (blockDim.x + 31) >> 5;
        for (int w = 0; w < nw; ++w) {
            a0 += (double)sred[w * 5 + 0];
            a1 += (double)sred[w * 5 + 1];
            a2 += (double)sred[w * 5 + 2];
            a3 += (double)sred[w * 5 + 3];
            a4 += (double)sred[w * 5 + 4];
        }
        atomicAdd(&g_acc[0], a0);
        atomicAdd(&g_acc[1], a1);
        atomicAdd(&g_acc[2], a2);
        atomicAdd(&g_acc[3], a3);
        atomicAdd(&g_acc[4], a4);
    }
}

__global__ void fcos_finalize_kernel(float* __restrict__ out, int B) {
    if (threadIdx.x == 0) {
        const double np = g_acc[4];
        out[0] = (float)(g_acc[0] / (np + (double)B));
        out[1] = (float)(g_acc[1] / fmax(g_acc[2], 1e-8));
        out[2] = (float)(g_acc[3] / fmax(np, 1.0));
    }
}

extern "C" void kernel_launch(void* const* d_in, const int* in_sizes, int n_in,
                              void* d_out, int out_size) {
    // Input order (metadata): locations, cls_pred, box_pred, center_pred,
    //                         bboxes, gt_labels, gt_centers, strides_pt, soi
    const float* loc         = (const float*)d_in[0];
    const float* cls_pred    = (const float*)d_in[1];
    const float* box_pred    = (const float*)d_in[2];
    const float* center_pred = (const float*)d_in[3];
    const float* bboxes      = (const float*)d_in[4];
    const int*   gt_labels   = (const int*)  d_in[5];
    // d_in[6] = gt_centers (unused by reference)
    const float* spt         = (const float*)d_in[7];
    const float* soi         = (const float*)d_in[8];

    const int N = in_sizes[7];                 // strides_pt has N elements
    const int B = in_sizes[3] / N;             // center_pred is B*N
    const int G = in_sizes[5] / B;             // gt_labels is B*G
    const int C = in_sizes[1] / (B * N);       // cls_pred is B*N*C

    fcos_zero_kernel<<<1, 32>>>();

    dim3 grid((N + 255) / 256, B);
    fcos_main_kernel<<<grid, 256>>>(loc, cls_pred, box_pred, center_pred,
                                    bboxes, gt_labels, spt, soi, N, G, C);

    fcos_finalize_kernel<<<1, 32>>>((float*)d_out, B);
}

// round 6
// speedup vs baseline: 1.2427x; 1.2427x over previous
#include <cuda_runtime.h>
#include <math.h>

#define FCOS_INF 1000000000.0f
#define MAXG 64
#define MAXBLK 4096

// Per-block partials: [blk*5 + {cls, box_w, w, center, npos}]
__device__ float g_part[MAXBLK * 5];
__device__ unsigned int g_count;   // zero-init; reset by last block each launch

template <int GS>  // GS > 0: compile-time G; GS == 0: runtime G
__global__ void __launch_bounds__(256)
fcos_fused_kernel(const float* __restrict__ loc,
                  const float* __restrict__ cls_pred,
                  const float* __restrict__ box_pred,
                  const float* __restrict__ center_pred,
                  const float* __restrict__ bboxes,
                  const int*   __restrict__ gt_labels,
                  const float* __restrict__ spt,
                  const float* __restrict__ soi,
                  float* __restrict__ out,
                  int N, int G_rt) {
    const int G = (GS > 0) ? GS : G_rt;

    // 8 floats per box: b0..b5, area, label(bits)
    __shared__ float sbox[MAXG * 8];
    __shared__ float sred[8 * 5];
    __shared__ bool  s_last;

    const int b   = blockIdx.y;
    const int tid = threadIdx.x;

    for (int t = tid; t < G * 6; t += blockDim.x)
        sbox[(t / 6) * 8 + (t % 6)] = bboxes[b * G * 6 + t];
    __syncthreads();
    for (int t = tid; t < G; t += blockDim.x) {
        const float* q = sbox + t * 8;
        sbox[t * 8 + 6] = (q[3] - q[0]) * (q[4] - q[1]) * (q[5] - q[2]);
        sbox[t * 8 + 7] = __int_as_float(gt_labels[b * G + t]);
    }
    __syncthreads();

    const int i = blockIdx.x * blockDim.x + tid;

    float cls_sum = 0.f, box_sum = 0.f, w_sum = 0.f, ctr_sum = 0.f, npos = 0.f;

    if (i < N) {
        const float x = loc[i * 3 + 0];
        const float y = loc[i * 3 + 1];
        const float z = loc[i * 3 + 2];
        const float s  = spt[i];
        const float lo = soi[i * 2 + 0];
        const float hi = soi[i * 2 + 1];

        float best = FCOS_INF;
        int bg = -1;

        #pragma unroll 4
        for (int g = 0; g < G; ++g) {
            const float4 v0 = *reinterpret_cast<const float4*>(sbox + g * 8);
            const float4 v1 = *reinterpret_cast<const float4*>(sbox + g * 8 + 4);

            const float el = x - v0.x, et = y - v0.y, ef = z - v0.z;
            const float er = v0.w - x, eb = v1.x - y, ea = v1.y - z;

            const float mx = fmaxf(fmaxf(fmaxf(el, et), fmaxf(ef, er)), fmaxf(eb, ea));
            const float mn = fminf(fminf(fminf(el, et), fminf(ef, er)), fminf(eb, ea));

            // dx = x - (b0+b3)/2 via two FMAs
            float dx = fmaf(-0.5f, v0.x, x); dx = fmaf(-0.5f, v0.w, dx);
            float dy = fmaf(-0.5f, v0.y, y); dy = fmaf(-0.5f, v1.x, dy);
            float dz = fmaf(-0.5f, v0.z, z); dz = fmaf(-0.5f, v1.y, dz);
            const float ma = fmaxf(fmaxf(fabsf(dx), fabsf(dy)), fabsf(dz));

            const bool ok = (mn > 0.0f) & (ma < s) & (mx >= lo) & (mx <= hi);
            const float ar = ok ? v1.z : FCOS_INF;
            if (ar < best) { best = ar; bg = g; }   // strict < == first-occurrence argmin
        }

        int label = 0;
        float Tl = 1.f, Tt = 1.f, Tf = 1.f, Tr = 1.f, Tb = 1.f, Ta = 1.f;
        if (bg >= 0) {
            const float4 v0 = *reinterpret_cast<const float4*>(sbox + bg * 8);
            const float4 v1 = *reinterpret_cast<const float4*>(sbox + bg * 8 + 4);
            Tl = x - v0.x; Tt = y - v0.y; Tf = z - v0.z;
            Tr = v0.w - x; Tb = v1.x - y; Ta = v1.y - z;
            label = __float_as_int(v1.w);
        }

        // ---- focal loss, C=8 classes ----
        const float4 c0 = *reinterpret_cast<const float4*>(cls_pred + ((size_t)b * N + i) * 8);
        const float4 c1 = *reinterpret_cast<const float4*>(cls_pred + ((size_t)b * N + i) * 8 + 4);
        const float cl[8] = {c0.x, c0.y, c0.z, c0.w, c1.x, c1.y, c1.z, c1.w};
        #pragma unroll
        for (int c = 0; c < 8; ++c) {
            const float xl = cl[c];
            const float t  = __expf(-fabsf(xl));
            const float u  = 1.0f + t;
            const float L  = __logf(u);                 // log1p(e^{-|x|})
            const float r  = __fdividef(1.0f, u);
            const float p  = (xl >= 0.0f) ? r : t * r;  // sigmoid(xl)
            const bool posc = (label == c + 1);
            const float q    = posc ? (1.0f - p) : p;
            const float lin  = posc ? -fminf(xl, 0.0f) : fmaxf(xl, 0.0f);
            const float coef = posc ? 0.25f : 0.75f;
            cls_sum += coef * q * q * (L + lin);
        }

        // ---- box + centerness (positives only) ----
        if (label > 0) {
            const float lrmn = fminf(Tl, Tr), lrmx = fmaxf(Tl, Tr);
            const float tbmn = fminf(Tt, Tb), tbmx = fmaxf(Tt, Tb);
            const float fbmn = fminf(Tf, Ta), fbmx = fmaxf(Tf, Ta);
            float cc = __fdividef(lrmn, lrmx) * __fdividef(tbmn, tbmx) * __fdividef(fbmn, fbmx);
            cc = fminf(fmaxf(cc, 1e-8f), 1.0f);
            const float ctr_t = sqrtf(cc);

            const float2 q0 = *reinterpret_cast<const float2*>(box_pred + ((size_t)b * N + i) * 6);
            const float2 q1 = *reinterpret_cast<const float2*>(box_pred + ((size_t)b * N + i) * 6 + 2);
            const float2 q2 = *reinterpret_cast<const float2*>(box_pred + ((size_t)b * N + i) * 6 + 4);
            const float p0 = q0.x, p1 = q0.y, p2 = q1.x;
            const float p3 = q1.y, p4 = q2.x, p5 = q2.y;

            const float pv = (p0 + p3) * (p1 + p4) * (p2 + p5);
            const float tv = (Tl + Tr) * (Tt + Tb) * (Tf + Ta);
            const float inter = (fminf(p0, Tl) + fminf(p3, Tr)) *
                                (fminf(p1, Tt) + fminf(p4, Tb)) *
                                (fminf(p2, Tf) + fminf(p5, Ta));
            const float uni = pv + tv - inter;
            const float iou = __fdividef(inter + 1.0f, uni + 1.0f);
            const float iou_loss = -__logf(fmaxf(iou, 1e-6f));

            box_sum += iou_loss * ctr_t;
            w_sum   += ctr_t;

            const float ct = center_pred[(size_t)b * N + i];
            const float bce = fmaxf(ct, 0.0f) - ct * ctr_t + __logf(1.0f + __expf(-fabsf(ct)));
            ctr_sum += bce;
            npos += 1.0f;
        }
    }

    // ---- block reduce (warp shuffle + smem) ----
    #pragma unroll
    for (int off = 16; off > 0; off >>= 1) {
        cls_sum += __shfl_down_sync(0xffffffffu, cls_sum, off);
        box_sum += __shfl_down_sync(0xffffffffu, box_sum, off);
        w_sum   += __shfl_down_sync(0xffffffffu, w_sum,   off);
        ctr_sum += __shfl_down_sync(0xffffffffu, ctr_sum, off);
        npos    += __shfl_down_sync(0xffffffffu, npos,    off);
    }
    const int lane = tid & 31;
    const int wid  = tid >> 5;
    if (lane == 0) {
        sred[wid * 5 + 0] = cls_sum;
        sred[wid * 5 + 1] = box_sum;
        sred[wid * 5 + 2] = w_sum;
        sred[wid * 5 + 3] = ctr_sum;
        sred[wid * 5 + 4] = npos;
    }
    __syncthreads();

    const int nblk = gridDim.x * gridDim.y;
    const int bid  = blockIdx.y * gridDim.x + blockIdx.x;

    if (tid == 0) {
        float a0 = 0, a1 = 0, a2 = 0, a3 = 0, a4 = 0;
        const int nw = (blockDim.x + 31) >> 5;
        for (int w = 0; w < nw; ++w) {
            a0 += sred[w * 5 + 0];
            a1 += sred[w * 5 + 1];
            a2 += sred[w * 5 + 2];
            a3 += sred[w * 5 + 3];
            a4 += sred[w * 5 + 4];
        }
        g_part[bid * 5 + 0] = a0;
        g_part[bid * 5 + 1] = a1;
        g_part[bid * 5 + 2] = a2;
        g_part[bid * 5 + 3] = a3;
        g_part[bid * 5 + 4] = a4;
        __threadfence();
        const unsigned v = atomicAdd(&g_count, 1u);
        s_last = (v == (unsigned)(nblk - 1));
    }
    __syncthreads();

    // ---- last block: final reduction + output ----
    if (s_last) {
        double a0 = 0, a1 = 0, a2 = 0, a3 = 0, a4 = 0;
        for (int k = tid; k < nblk; k += blockDim.x) {
            a0 += (double)g_part[k * 5 + 0];
            a1 += (double)g_part[k * 5 + 1];
            a2 += (double)g_part[k * 5 + 2];
            a3 += (double)g_part[k * 5 + 3];
            a4 += (double)g_part[k * 5 + 4];
        }
        #pragma unroll
        for (int off = 16; off > 0; off >>= 1) {
            a0 += __shfl_down_sync(0xffffffffu, a0, off);
            a1 += __shfl_down_sync(0xffffffffu, a1, off);
            a2 += __shfl_down_sync(0xffffffffu, a2, off);
            a3 += __shfl_down_sync(0xffffffffu, a3, off);
            a4 += __shfl_down_sync(0xffffffffu, a4, off);
        }
        __shared__ double dred[8 * 5];
        if (lane == 0) {
            dred[wid * 5 + 0] = a0; dred[wid * 5 + 1] = a1; dred[wid * 5 + 2] = a2;
            dred[wid * 5 + 3] = a3; dred[wid * 5 + 4] = a4;
        }
        __syncthreads();
        if (tid == 0) {
            double t0 = 0, t1 = 0, t2 = 0, t3 = 0, t4 = 0;
            const int nw = (blockDim.x + 31) >> 5;
            for (int w = 0; w < nw; ++w) {
                t0 += dred[w * 5 + 0]; t1 += dred[w * 5 + 1]; t2 += dred[w * 5 + 2];
                t3 += dred[w * 5 + 3]; t4 += dred[w * 5 + 4];
            }
            const double B = (double)gridDim.y;
            out[0] = (float)(t0 / (t4 + B));
            out[1] = (float)(t1 / fmax(t2, 1e-8));
            out[2] = (float)(t3 / fmax(t4, 1.0));
            g_count = 0;   // reset for next graph replay
        }
    }
}

extern "C" void kernel_launch(void* const* d_in, const int* in_sizes, int n_in,
                              void* d_out, int out_size) {
    const float* loc         = (const float*)d_in[0];
    const float* cls_pred    = (const float*)d_in[1];
    const float* box_pred    = (const float*)d_in[2];
    const float* center_pred = (const float*)d_in[3];
    const float* bboxes      = (const float*)d_in[4];
    const int*   gt_labels   = (const int*)  d_in[5];
    const float* spt         = (const float*)d_in[7];
    const float* soi         = (const float*)d_in[8];

    const int N = in_sizes[7];
    const int B = in_sizes[3] / N;
    const int G = in_sizes[5] / B;

    dim3 grid((N + 255) / 256, B);
    if (G == 48) {
        fcos_fused_kernel<48><<<grid, 256>>>(loc, cls_pred, box_pred, center_pred,
                                             bboxes, gt_labels, spt, soi,
                                             (float*)d_out, N, G);
    } else {
        fcos_fused_kernel<0><<<grid, 256>>>(loc, cls_pred, box_pred, center_pred,
                                            bboxes, gt_labels, spt, soi,
                                            (float*)d_out, N, G);
    }
}

// round 10
// speedup vs baseline: 1.3653x; 1.0986x over previous
#include <cuda_runtime.h>
#include <math.h>

#define FCOS_INF 1000000000.0f
#define MAXG 64
#define MAXBLK 4096

// Per-block partials: [blk*5 + {cls, box_w, w, center, npos}]
__device__ float g_part[MAXBLK * 5];
__device__ unsigned int g_count;   // zero-init; reset by last block each launch

template <int GS>  // GS > 0: compile-time G; GS == 0: runtime G
__global__ void __launch_bounds__(256)
fcos_fused_kernel(const float* __restrict__ loc,
                  const float* __restrict__ cls_pred,
                  const float* __restrict__ box_pred,
                  const float* __restrict__ center_pred,
                  const float* __restrict__ bboxes,
                  const int*   __restrict__ gt_labels,
                  const float* __restrict__ spt,
                  const float* __restrict__ soi,
                  float* __restrict__ out,
                  int N, int G_rt) {
    const int G = (GS > 0) ? GS : G_rt;

    // 12 floats per box: b0..b5, cx, cy, cz, area, label(bits), pad
    __shared__ float sbox[MAXG * 12];
    __shared__ float sred[8 * 5];
    __shared__ bool  s_last;

    const int b   = blockIdx.y;
    const int tid = threadIdx.x;

    for (int t = tid; t < G * 6; t += blockDim.x)
        sbox[(t / 6) * 12 + (t % 6)] = bboxes[b * G * 6 + t];
    __syncthreads();
    for (int t = tid; t < G; t += blockDim.x) {
        float* q = sbox + t * 12;
        q[6]  = (q[0] + q[3]) * 0.5f;   // cx
        q[7]  = (q[1] + q[4]) * 0.5f;   // cy
        q[8]  = (q[2] + q[5]) * 0.5f;   // cz
        q[9]  = (q[3] - q[0]) * (q[4] - q[1]) * (q[5] - q[2]);  // area
        q[10] = __int_as_float(gt_labels[b * G + t]);
        q[11] = 0.0f;
    }
    __syncthreads();

    // Two locations per thread for ILP
    const int i0 = blockIdx.x * (2 * blockDim.x) + tid;
    const int i1 = i0 + blockDim.x;
    const int idx[2]   = {i0, i1};
    const bool valid0  = (i0 < N);
    const bool valid1  = (i1 < N);
    const bool valid[2] = {valid0, valid1};

    float X[2] = {0.f, 0.f}, Y[2] = {0.f, 0.f}, Z[2] = {0.f, 0.f};
    float S[2] = {0.f, 0.f}, LO[2] = {0.f, 0.f}, HI[2] = {0.f, 0.f};
    #pragma unroll
    for (int j = 0; j < 2; ++j) {
        if (valid[j]) {
            X[j]  = loc[idx[j] * 3 + 0];
            Y[j]  = loc[idx[j] * 3 + 1];
            Z[j]  = loc[idx[j] * 3 + 2];
            S[j]  = spt[idx[j]];
            LO[j] = soi[idx[j] * 2 + 0];
            HI[j] = soi[idx[j] * 2 + 1];
        }
    }

    float best[2] = {FCOS_INF, FCOS_INF};
    int   bg[2]   = {-1, -1};

    #pragma unroll 4
    for (int g = 0; g < G; ++g) {
        const float4 v0 = *reinterpret_cast<const float4*>(sbox + g * 12);      // b0..b3
        const float4 v1 = *reinterpret_cast<const float4*>(sbox + g * 12 + 4);  // b4,b5,cx,cy
        const float4 v2 = *reinterpret_cast<const float4*>(sbox + g * 12 + 8);  // cz,area,label,pad

        #pragma unroll
        for (int j = 0; j < 2; ++j) {
            const float el = X[j] - v0.x, et = Y[j] - v0.y, ef = Z[j] - v0.z;
            const float er = v0.w - X[j], eb = v1.x - Y[j], ea = v1.y - Z[j];

            const float mx = fmaxf(fmaxf(fmaxf(el, et), fmaxf(ef, er)), fmaxf(eb, ea));
            const float mn = fminf(fminf(fminf(el, et), fminf(ef, er)), fminf(eb, ea));

            const float dx = X[j] - v1.z;
            const float dy = Y[j] - v1.w;
            const float dz = Z[j] - v2.x;
            const float ma = fmaxf(fmaxf(fabsf(dx), fabsf(dy)), fabsf(dz));

            const bool ok = (mn > 0.0f) & (ma < S[j]) & (mx >= LO[j]) & (mx <= HI[j]);
            const float ar = ok ? v2.y : FCOS_INF;
            if (ar < best[j]) { best[j] = ar; bg[j] = g; }   // strict < == first-occurrence
        }
    }

    float cls_sum = 0.f, box_sum = 0.f, w_sum = 0.f, ctr_sum = 0.f, npos = 0.f;

    #pragma unroll
    for (int j = 0; j < 2; ++j) {
        if (!valid[j]) continue;
        const int i = idx[j];
        const float x = X[j], y = Y[j], z = Z[j];

        int label = 0;
        float Tl = 1.f, Tt = 1.f, Tf = 1.f, Tr = 1.f, Tb = 1.f, Ta = 1.f;
        if (bg[j] >= 0) {
            const float4 v0 = *reinterpret_cast<const float4*>(sbox + bg[j] * 12);
            const float4 v1 = *reinterpret_cast<const float4*>(sbox + bg[j] * 12 + 4);
            Tl = x - v0.x; Tt = y - v0.y; Tf = z - v0.z;
            Tr = v0.w - x; Tb = v1.x - y; Ta = v1.y - z;
            label = __float_as_int(sbox[bg[j] * 12 + 10]);
        }

        // ---- focal loss, C=8 classes ----
        const float4 c0 = *reinterpret_cast<const float4*>(cls_pred + ((size_t)b * N + i) * 8);
        const float4 c1 = *reinterpret_cast<const float4*>(cls_pred + ((size_t)b * N + i) * 8 + 4);
        const float cl[8] = {c0.x, c0.y, c0.z, c0.w, c1.x, c1.y, c1.z, c1.w};
        #pragma unroll
        for (int c = 0; c < 8; ++c) {
            const float xl = cl[c];
            const float t  = __expf(-fabsf(xl));
            const float u  = 1.0f + t;
            const float L  = __logf(u);                 // log1p(e^{-|x|})
            const float r  = __fdividef(1.0f, u);
            const float p  = (xl >= 0.0f) ? r : t * r;  // sigmoid(xl)
            const bool posc = (label == c + 1);
            const float q    = posc ? (1.0f - p) : p;
            const float lin  = posc ? -fminf(xl, 0.0f) : fmaxf(xl, 0.0f);
            const float coef = posc ? 0.25f : 0.75f;
            cls_sum += coef * q * q * (L + lin);
        }

        // ---- box + centerness (positives only) ----
        if (label > 0) {
            const float lrmn = fminf(Tl, Tr), lrmx = fmaxf(Tl, Tr);
            const float tbmn = fminf(Tt, Tb), tbmx = fmaxf(Tt, Tb);
            const float fbmn = fminf(Tf, Ta), fbmx = fmaxf(Tf, Ta);
            float cc = __fdividef(lrmn, lrmx) * __fdividef(tbmn, tbmx) * __fdividef(fbmn, fbmx);
            cc = fminf(fmaxf(cc, 1e-8f), 1.0f);
            const float ctr_t = sqrtf(cc);

            const float2 q0 = *reinterpret_cast<const float2*>(box_pred + ((size_t)b * N + i) * 6);
            const float2 q1 = *reinterpret_cast<const float2*>(box_pred + ((size_t)b * N + i) * 6 + 2);
            const float2 q2 = *reinterpret_cast<const float2*>(box_pred + ((size_t)b * N + i) * 6 + 4);
            const float p0 = q0.x, p1 = q0.y, p2 = q1.x;
            const float p3 = q1.y, p4 = q2.x, p5 = q2.y;

            const float pv = (p0 + p3) * (p1 + p4) * (p2 + p5);
            const float tv = (Tl + Tr) * (Tt + Tb) * (Tf + Ta);
            const float inter = (fminf(p0, Tl) + fminf(p3, Tr)) *
                                (fminf(p1, Tt) + fminf(p4, Tb)) *
                                (fminf(p2, Tf) + fminf(p5, Ta));
            const float uni = pv + tv - inter;
            const float iou = __fdividef(inter + 1.0f, uni + 1.0f);
            const float iou_loss = -__logf(fmaxf(iou, 1e-6f));

            box_sum += iou_loss * ctr_t;
            w_sum   += ctr_t;

            const float ct = center_pred[(size_t)b * N + i];
            const float bce = fmaxf(ct, 0.0f) - ct * ctr_t + __logf(1.0f + __expf(-fabsf(ct)));
            ctr_sum += bce;
            npos += 1.0f;
        }
    }

    // ---- block reduce (warp shuffle + smem) ----
    #pragma unroll
    for (int off = 16; off > 0; off >>= 1) {
        cls_sum += __shfl_down_sync(0xffffffffu, cls_sum, off);
        box_sum += __shfl_down_sync(0xffffffffu, box_sum, off);
        w_sum   += __shfl_down_sync(0xffffffffu, w_sum,   off);
        ctr_sum += __shfl_down_sync(0xffffffffu, ctr_sum, off);
        npos    += __shfl_down_sync(0xffffffffu, npos,    off);
    }
    const int lane = tid & 31;
    const int wid  = tid >> 5;
    if (lane == 0) {
        sred[wid * 5 + 0] = cls_sum;
        sred[wid * 5 + 1] = box_sum;
        sred[wid * 5 + 2] = w_sum;
        sred[wid * 5 + 3] = ctr_sum;
        sred[wid * 5 + 4] = npos;
    }
    __syncthreads();

    const int nblk = gridDim.x * gridDim.y;
    const int bid  = blockIdx.y * gridDim.x + blockIdx.x;

    if (tid == 0) {
        float a0 = 0, a1 = 0, a2 = 0, a3 = 0, a4 = 0;
        const int nw = (blockDim.x + 31) >> 5;
        for (int w = 0; w < nw; ++w) {
            a0 += sred[w * 5 + 0];
            a1 += sred[w * 5 + 1];
            a2 += sred[w * 5 + 2];
            a3 += sred[w * 5 + 3];
            a4 += sred[w * 5 + 4];
        }
        g_part[bid * 5 + 0] = a0;
        g_part[bid * 5 + 1] = a1;
        g_part[bid * 5 + 2] = a2;
        g_part[bid * 5 + 3] = a3;
        g_part[bid * 5 + 4] = a4;
        __threadfence();
        const unsigned v = atomicAdd(&g_count, 1u);
        s_last = (v == (unsigned)(nblk - 1));
    }
    __syncthreads();

    // ---- last block: final reduction + output ----
    if (s_last) {
        double a0 = 0, a1 = 0, a2 = 0, a3 = 0, a4 = 0;
        for (int k = tid; k < nblk; k += blockDim.x) {
            a0 += (double)g_part[k * 5 + 0];
            a1 += (double)g_part[k * 5 + 1];
            a2 += (double)g_part[k * 5 + 2];
            a3 += (double)g_part[k * 5 + 3];
            a4 += (double)g_part[k * 5 + 4];
        }
        #pragma unroll
        for (int off = 16; off > 0; off >>= 1) {
            a0 += __shfl_down_sync(0xffffffffu, a0, off);
            a1 += __shfl_down_sync(0xffffffffu, a1, off);
            a2 += __shfl_down_sync(0xffffffffu, a2, off);
            a3 += __shfl_down_sync(0xffffffffu, a3, off);
            a4 += __shfl_down_sync(0xffffffffu, a4, off);
        }
        __shared__ double dred[8 * 5];
        if (lane == 0) {
            dred[wid * 5 + 0] = a0; dred[wid * 5 + 1] = a1; dred[wid * 5 + 2] = a2;
            dred[wid * 5 + 3] = a3; dred[wid * 5 + 4] = a4;
        }
        __syncthreads();
        if (tid == 0) {
            double t0 = 0, t1 = 0, t2 = 0, t3 = 0, t4 = 0;
            const int nw = (blockDim.x + 31) >> 5;
            for (int w = 0; w < nw; ++w) {
                t0 += dred[w * 5 + 0]; t1 += dred[w * 5 + 1]; t2 += dred[w * 5 + 2];
                t3 += dred[w * 5 + 3]; t4 += dred[w * 5 + 4];
            }
            const double B = (double)gridDim.y;
            out[0] = (float)(t0 / (t4 + B));
            out[1] = (float)(t1 / fmax(t2, 1e-8));
            out[2] = (float)(t3 / fmax(t4, 1.0));
            g_count = 0;   // reset for next graph replay
        }
    }
}

extern "C" void kernel_launch(void* const* d_in, const int* in_sizes, int n_in,
                              void* d_out, int out_size) {
    const float* loc         = (const float*)d_in[0];
    const float* cls_pred    = (const float*)d_in[1];
    const float* box_pred    = (const float*)d_in[2];
    const float* center_pred = (const float*)d_in[3];
    const float* bboxes      = (const float*)d_in[4];
    const int*   gt_labels   = (const int*)  d_in[5];
    const float* spt         = (const float*)d_in[7];
    const float* soi         = (const float*)d_in[8];

    const int N = in_sizes[7];
    const int B = in_sizes[3] / N;
    const int G = in_sizes[5] / B;

    dim3 grid((N + 511) / 512, B);   // 2 locations per thread
    if (G == 48) {
        fcos_fused_kernel<48><<<grid, 256>>>(loc, cls_pred, box_pred, center_pred,
                                             bboxes, gt_labels, spt, soi,
                                             (float*)d_out, N, G);
    } else {
        fcos_fused_kernel<0><<<grid, 256>>>(loc, cls_pred, box_pred, center_pred,
                                            bboxes, gt_labels, spt, soi,
                                            (float*)d_out, N, G);
    }
}